// round 2
// baseline (speedup 1.0000x reference)
#include <cuda_runtime.h>

#define NN 100000
#define EE 800000

// ---------------- scratch (device globals; no allocation allowed) ----------------
__device__ float g_h1[NN * 64];
__device__ float g_h2[NN * 64];
__device__ float g_p[NN * 64];
__device__ float g_g[NN * 128];
__device__ float g_asrc[NN * 2];
__device__ float g_adst[NN * 2];
__device__ unsigned g_m[NN * 2];
__device__ float g_denom[NN * 2];
__device__ float g_num[NN * 128];
__device__ float g_Wn[3][64 * 64];
__device__ float g_We[3][5 * 64];
__device__ float g_bp[3][64];

// ---------------- helpers ----------------
__device__ __forceinline__ unsigned ordF(float f) {
    unsigned u = __float_as_uint(f);
    return (u & 0x80000000u) ? ~u : (u | 0x80000000u);
}
__device__ __forceinline__ float deOrdF(unsigned u) {
    return __uint_as_float((u & 0x80000000u) ? (u & 0x7fffffffu) : ~u);
}
__device__ __forceinline__ float lrelu(float x) { return x > 0.f ? x : 0.2f * x; }

// ---------------- weight folding ----------------
// Wn' = wn @ wc_top ; We' = we @ wc_bot ; b' = bn@wc_top + be@wc_bot + bc
__global__ void fold_kernel(const float* __restrict__ wn, const float* __restrict__ bn,
                            const float* __restrict__ we, const float* __restrict__ be,
                            const float* __restrict__ wc, const float* __restrict__ bc,
                            float* __restrict__ Wn, float* __restrict__ We,
                            float* __restrict__ bp) {
    for (int t = blockIdx.x * blockDim.x + threadIdx.x; t < 64 * 64 + 5 * 64 + 64;
         t += gridDim.x * blockDim.x) {
        if (t < 4096) {
            int r = t >> 6, c = t & 63;
            float s = 0.f;
            #pragma unroll 8
            for (int k = 0; k < 64; k++) s += wn[r * 64 + k] * wc[k * 64 + c];
            Wn[t] = s;
        } else if (t < 4096 + 320) {
            int u = t - 4096;
            int j = u >> 6, c = u & 63;
            float s = 0.f;
            #pragma unroll 8
            for (int k = 0; k < 64; k++) s += we[j * 64 + k] * wc[(64 + k) * 64 + c];
            We[u] = s;
        } else {
            int c = t - 4416;
            float s = bc[c];
            #pragma unroll 8
            for (int k = 0; k < 64; k++)
                s += bn[k] * wc[k * 64 + c] + be[k] * wc[(64 + k) * 64 + c];
            bp[c] = s;
        }
    }
}

// ---------------- dense GEMM: C[n0:n0+64, c0b:c0b+64] = (relu?)A @ W ----------------
// A: n x 64 (ld 64), W: 64 x ldw, C: n x ldw
__global__ void gemm_kernel(const float* __restrict__ A, const float* __restrict__ W,
                            float* __restrict__ C, int n, int relu, int ldw) {
    __shared__ float hsT[64][68];   // transposed A tile (k-major), pitch 68 for alignment
    __shared__ float Ws[64][64];
    int n0 = blockIdx.x << 6;
    int c0b = blockIdx.y << 6;
    int t = threadIdx.x;

    #pragma unroll
    for (int i = 0; i < 4; i++) {
        int idx = t + i * 256;
        int row = idx >> 4;
        int k4 = (idx & 15) << 2;
        float4 v = make_float4(0.f, 0.f, 0.f, 0.f);
        if (n0 + row < n) v = *(const float4*)(A + (size_t)(n0 + row) * 64 + k4);
        if (relu) {
            v.x = fmaxf(v.x, 0.f); v.y = fmaxf(v.y, 0.f);
            v.z = fmaxf(v.z, 0.f); v.w = fmaxf(v.w, 0.f);
        }
        hsT[k4 + 0][row] = v.x; hsT[k4 + 1][row] = v.y;
        hsT[k4 + 2][row] = v.z; hsT[k4 + 3][row] = v.w;
    }
    #pragma unroll
    for (int i = 0; i < 4; i++) {
        int idx = t + i * 256;
        int k = idx >> 4;
        int c4 = (idx & 15) << 2;
        *(float4*)&Ws[k][c4] = *(const float4*)(W + (size_t)k * ldw + c0b + c4);
    }
    __syncthreads();

    int tx = t & 15, ty = t >> 4;
    int r0 = ty << 2, c0 = tx << 2;
    float acc[4][4];
    #pragma unroll
    for (int i = 0; i < 4; i++)
        #pragma unroll
        for (int j = 0; j < 4; j++) acc[i][j] = 0.f;

    #pragma unroll
    for (int k = 0; k < 64; k++) {
        float4 a = *(float4*)&hsT[k][r0];
        float4 b = *(float4*)&Ws[k][c0];
        acc[0][0] += a.x * b.x; acc[0][1] += a.x * b.y; acc[0][2] += a.x * b.z; acc[0][3] += a.x * b.w;
        acc[1][0] += a.y * b.x; acc[1][1] += a.y * b.y; acc[1][2] += a.y * b.z; acc[1][3] += a.y * b.w;
        acc[2][0] += a.z * b.x; acc[2][1] += a.z * b.y; acc[2][2] += a.z * b.z; acc[2][3] += a.z * b.w;
        acc[3][0] += a.w * b.x; acc[3][1] += a.w * b.y; acc[3][2] += a.w * b.z; acc[3][3] += a.w * b.w;
    }

    #pragma unroll
    for (int i = 0; i < 4; i++) {
        int row = n0 + r0 + i;
        if (row < n) {
            float4 o = make_float4(acc[i][0], acc[i][1], acc[i][2], acc[i][3]);
            *(float4*)(C + (size_t)row * ldw + c0b + c0) = o;
        }
    }
}

// ---------------- zero fill ----------------
__global__ void zero4_kernel(float4* __restrict__ p, int n4) {
    float4 z = make_float4(0.f, 0.f, 0.f, 0.f);
    for (int i = blockIdx.x * blockDim.x + threadIdx.x; i < n4; i += gridDim.x * blockDim.x)
        p[i] = z;
}

// ---------------- edge conv: out[dst] += p[src] + ea @ We' + b' ----------------
// 1 warp per edge, 8 edges per 256-thread block. Grid = EE/8 exactly.
__global__ void edge_conv_kernel(const float* __restrict__ p, const int* __restrict__ src,
                                 const int* __restrict__ dst, const float* __restrict__ ea,
                                 const float* __restrict__ We, const float* __restrict__ bp,
                                 float* __restrict__ out) {
    __shared__ float sWe[5 * 64];
    __shared__ float sbp[64];
    int t = threadIdx.x;
    // 384 shared floats loaded by 256 threads -> strided loop (Round-1 bug fix)
    for (int i = t; i < 384; i += 256) {
        if (i < 320) sWe[i] = We[i];
        else sbp[i - 320] = bp[i - 320];
    }
    __syncthreads();

    int e = blockIdx.x * 8 + (t >> 5);
    int lane = t & 31;
    int s = src[e], d = dst[e];
    const float* eap = ea + (size_t)e * 5;
    float e0 = eap[0], e1 = eap[1], e2 = eap[2], e3 = eap[3], e4 = eap[4];
    const float* pr = p + (size_t)s * 64;
    float* orow = out + (size_t)d * 64;
    #pragma unroll
    for (int cc = 0; cc < 2; cc++) {
        int c = lane + cc * 32;
        float m = pr[c] + sbp[c] + e0 * sWe[c] + e1 * sWe[64 + c] + e2 * sWe[128 + c] +
                  e3 * sWe[192 + c] + e4 * sWe[256 + c];
        atomicAdd(orow + c, m);
    }
}

// ---------------- GAT attention coefficients: a = g . att ----------------
// 1 warp per node. Grid*8 must cover NN.
__global__ void attn_kernel(const float* __restrict__ g, const float* __restrict__ att_src,
                            const float* __restrict__ att_dst, float* __restrict__ asrc,
                            float* __restrict__ adst, int n) {
    int w = (blockIdx.x * blockDim.x + threadIdx.x) >> 5;
    int lane = threadIdx.x & 31;
    if (w >= n) return;
    const float* gr = g + (size_t)w * 128;
    float v0 = gr[lane], v1 = gr[lane + 32], v2 = gr[lane + 64], v3 = gr[lane + 96];
    float s0 = v0 * att_src[lane] + v1 * att_src[lane + 32];
    float s1 = v2 * att_src[64 + lane] + v3 * att_src[96 + lane];
    float d0 = v0 * att_dst[lane] + v1 * att_dst[lane + 32];
    float d1 = v2 * att_dst[64 + lane] + v3 * att_dst[96 + lane];
    #pragma unroll
    for (int o = 16; o; o >>= 1) {
        s0 += __shfl_down_sync(0xffffffffu, s0, o);
        s1 += __shfl_down_sync(0xffffffffu, s1, o);
        d0 += __shfl_down_sync(0xffffffffu, d0, o);
        d1 += __shfl_down_sync(0xffffffffu, d1, o);
    }
    if (lane == 0) {
        asrc[w * 2] = s0; asrc[w * 2 + 1] = s1;
        adst[w * 2] = d0; adst[w * 2 + 1] = d1;
    }
}

// ---------------- GAT pass 1: segment max via ordered-uint atomicMax ----------------
__global__ void gat_max_kernel(const int* __restrict__ src, const int* __restrict__ dst,
                               const float* __restrict__ asrc, const float* __restrict__ adst,
                               unsigned* __restrict__ m) {
    int e = blockIdx.x * blockDim.x + threadIdx.x;
    if (e >= EE) return;
    int s = src[e], d = dst[e];
    float a0 = lrelu(asrc[s * 2] + adst[d * 2]);
    float a1 = lrelu(asrc[s * 2 + 1] + adst[d * 2 + 1]);
    atomicMax(&m[d * 2], ordF(a0));
    atomicMax(&m[d * 2 + 1], ordF(a1));
}

// ---------------- GAT pass 2: accumulate exp weights + weighted features ----------------
// 1 warp per edge.
__global__ void gat_acc_kernel(const int* __restrict__ src, const int* __restrict__ dst,
                               const float* __restrict__ asrc, const float* __restrict__ adst,
                               const unsigned* __restrict__ m, const float* __restrict__ g,
                               float* __restrict__ denom, float* __restrict__ num) {
    int t = threadIdx.x;
    int e = blockIdx.x * 8 + (t >> 5);
    int lane = t & 31;
    int s = src[e], d = dst[e];
    float a0 = lrelu(asrc[s * 2] + adst[d * 2]);
    float a1 = lrelu(asrc[s * 2 + 1] + adst[d * 2 + 1]);
    float w0 = expf(a0 - deOrdF(m[d * 2]));
    float w1 = expf(a1 - deOrdF(m[d * 2 + 1]));
    if (lane == 0) {
        atomicAdd(&denom[d * 2], w0);
        atomicAdd(&denom[d * 2 + 1], w1);
    }
    const float* gs = g + (size_t)s * 128;
    float* nd = num + (size_t)d * 128;
    atomicAdd(nd + lane, w0 * gs[lane]);
    atomicAdd(nd + lane + 32, w0 * gs[lane + 32]);
    atomicAdd(nd + lane + 64, w1 * gs[lane + 64]);
    atomicAdd(nd + lane + 96, w1 * gs[lane + 96]);
}

// ---------------- GAT final: mean over heads + bias ----------------
__global__ void gat_final_kernel(const float* __restrict__ num, const float* __restrict__ denom,
                                 const float* __restrict__ b_gat, float* __restrict__ out) {
    int i = blockIdx.x * blockDim.x + threadIdx.x;
    if (i >= NN * 64) return;
    int n = i >> 6, c = i & 63;
    float d0 = denom[n * 2] + 1e-16f;
    float d1 = denom[n * 2 + 1] + 1e-16f;
    out[i] = 0.5f * (num[(size_t)n * 128 + c] / d0 + num[(size_t)n * 128 + 64 + c] / d1) + b_gat[c];
}

// ---------------- launch ----------------
extern "C" void kernel_launch(void* const* d_in, const int* in_sizes, int n_in,
                              void* d_out, int out_size) {
    const float* x = (const float*)d_in[0];
    const int* ei = (const int*)d_in[1];
    const float* ea = (const float*)d_in[2];
    const int* src = ei;
    const int* dst = ei + EE;
    const float* Wp[18];
    for (int i = 0; i < 18; i++) Wp[i] = (const float*)d_in[3 + i];
    const float* w_gat = (const float*)d_in[21];
    const float* att_src = (const float*)d_in[22];
    const float* att_dst = (const float*)d_in[23];
    const float* b_gat = (const float*)d_in[24];
    float* out = (float*)d_out;

    float *h1, *h2, *p, *gg, *asrc, *adst, *denom, *num;
    unsigned* m;
    float *Wn, *We, *bp;
    cudaGetSymbolAddress((void**)&h1, g_h1);
    cudaGetSymbolAddress((void**)&h2, g_h2);
    cudaGetSymbolAddress((void**)&p, g_p);
    cudaGetSymbolAddress((void**)&gg, g_g);
    cudaGetSymbolAddress((void**)&asrc, g_asrc);
    cudaGetSymbolAddress((void**)&adst, g_adst);
    cudaGetSymbolAddress((void**)&m, g_m);
    cudaGetSymbolAddress((void**)&denom, g_denom);
    cudaGetSymbolAddress((void**)&num, g_num);
    cudaGetSymbolAddress((void**)&Wn, g_Wn);
    cudaGetSymbolAddress((void**)&We, g_We);
    cudaGetSymbolAddress((void**)&bp, g_bp);

    // fold weights for all 3 edge-conv layers
    for (int i = 0; i < 3; i++) {
        fold_kernel<<<18, 256>>>(Wp[6 * i + 0], Wp[6 * i + 1], Wp[6 * i + 2], Wp[6 * i + 3],
                                 Wp[6 * i + 4], Wp[6 * i + 5],
                                 Wn + i * 4096, We + i * 320, bp + i * 64);
    }

    const int gb = (NN + 63) / 64;   // 1563
    const int EB = EE / 8;           // 100000 warps-per-edge blocks

    // layer 1 (input = x, no relu on input)
    gemm_kernel<<<dim3(gb, 1), 256>>>(x, Wn + 0 * 4096, p, NN, 0, 64);
    zero4_kernel<<<2048, 256>>>((float4*)h1, NN * 16);
    edge_conv_kernel<<<EB, 256>>>(p, src, dst, ea, We + 0 * 320, bp + 0 * 64, h1);

    // layer 2 (relu fused into gemm input)
    gemm_kernel<<<dim3(gb, 1), 256>>>(h1, Wn + 1 * 4096, p, NN, 1, 64);
    zero4_kernel<<<2048, 256>>>((float4*)h2, NN * 16);
    edge_conv_kernel<<<EB, 256>>>(p, src, dst, ea, We + 1 * 320, bp + 1 * 64, h2);

    // layer 3
    gemm_kernel<<<dim3(gb, 1), 256>>>(h2, Wn + 2 * 4096, p, NN, 1, 64);
    zero4_kernel<<<2048, 256>>>((float4*)h1, NN * 16);
    edge_conv_kernel<<<EB, 256>>>(p, src, dst, ea, We + 2 * 320, bp + 2 * 64, h1);

    // GAT projection g = relu(h) @ w_gat  (64 -> 128, two column tiles)
    gemm_kernel<<<dim3(gb, 2), 256>>>(h1, w_gat, gg, NN, 1, 128);

    // attention coefficients
    attn_kernel<<<(NN + 7) / 8, 256>>>(gg, att_src, att_dst, asrc, adst, NN);

    // init m (ordered-uint 0 == below all reals), denom, num
    zero4_kernel<<<64, 256>>>((float4*)m, NN * 2 / 4);
    zero4_kernel<<<64, 256>>>((float4*)denom, NN * 2 / 4);
    zero4_kernel<<<2048, 256>>>((float4*)num, NN * 32);

    gat_max_kernel<<<EE / 256, 256>>>(src, dst, asrc, adst, m);
    gat_acc_kernel<<<EB, 256>>>(src, dst, asrc, adst, m, gg, denom, num);
    gat_final_kernel<<<NN * 64 / 256, 256>>>(num, denom, b_gat, out);
}

// round 3
// speedup vs baseline: 1.5449x; 1.5449x over previous
#include <cuda_runtime.h>

#define NN 100000
#define EE 800000

// ---------------- scratch (device globals; no allocation allowed) ----------------
__device__ float g_h1[NN * 64];
__device__ float g_h2[NN * 64];
__device__ float g_p[NN * 64];
__device__ float g_g[NN * 128];
__device__ float g_asrc[NN * 2];
__device__ float g_adst[NN * 2];
__device__ float g_Wn[3][64 * 64];
__device__ float g_We[3][5 * 64];
__device__ float g_bp[3][64];
// CSR scratch
__device__ int g_cnt[NN];
__device__ int g_cursor[NN];
__device__ int g_rowptr[NN + 4];
__device__ int g_csr_src[EE];
__device__ float g_S[NN * 5];

// ---------------- helpers ----------------
__device__ __forceinline__ float lrelu(float x) { return x > 0.f ? x : 0.2f * x; }

// ---------------- weight folding ----------------
__global__ void fold_kernel(const float* __restrict__ wn, const float* __restrict__ bn,
                            const float* __restrict__ we, const float* __restrict__ be,
                            const float* __restrict__ wc, const float* __restrict__ bc,
                            float* __restrict__ Wn, float* __restrict__ We,
                            float* __restrict__ bp) {
    for (int t = blockIdx.x * blockDim.x + threadIdx.x; t < 64 * 64 + 5 * 64 + 64;
         t += gridDim.x * blockDim.x) {
        if (t < 4096) {
            int r = t >> 6, c = t & 63;
            float s = 0.f;
            #pragma unroll 8
            for (int k = 0; k < 64; k++) s += wn[r * 64 + k] * wc[k * 64 + c];
            Wn[t] = s;
        } else if (t < 4096 + 320) {
            int u = t - 4096;
            int j = u >> 6, c = u & 63;
            float s = 0.f;
            #pragma unroll 8
            for (int k = 0; k < 64; k++) s += we[j * 64 + k] * wc[(64 + k) * 64 + c];
            We[u] = s;
        } else {
            int c = t - 4416;
            float s = bc[c];
            #pragma unroll 8
            for (int k = 0; k < 64; k++)
                s += bn[k] * wc[k * 64 + c] + be[k] * wc[(64 + k) * 64 + c];
            bp[c] = s;
        }
    }
}

// ---------------- zero fill ----------------
__global__ void zero4_kernel(float4* __restrict__ p, int n4) {
    float4 z = make_float4(0.f, 0.f, 0.f, 0.f);
    for (int i = blockIdx.x * blockDim.x + threadIdx.x; i < n4; i += gridDim.x * blockDim.x)
        p[i] = z;
}

// ---------------- CSR build ----------------
__global__ void count_kernel(const int* __restrict__ dst, int* __restrict__ cnt) {
    int e = blockIdx.x * blockDim.x + threadIdx.x;
    if (e < EE) atomicAdd(&cnt[dst[e]], 1);
}

// single-block chunked inclusive scan: rowptr[i+1] = sum cnt[0..i], rowptr[0]=0
__global__ void scan_kernel(const int* __restrict__ cnt, int* __restrict__ rowptr) {
    __shared__ int wsum[32];
    __shared__ int s_carry;
    int t = threadIdx.x;               // 1024 threads
    int lane = t & 31, wid = t >> 5;
    if (t == 0) { s_carry = 0; rowptr[0] = 0; }
    __syncthreads();
    for (int base = 0; base < NN; base += 8192) {
        int v[8];
        int idx0 = base + t * 8;
        #pragma unroll
        for (int j = 0; j < 8; j++) {
            int idx = idx0 + j;
            v[j] = (idx < NN) ? cnt[idx] : 0;
        }
        #pragma unroll
        for (int j = 1; j < 8; j++) v[j] += v[j - 1];
        int tot = v[7];
        int incl = tot;
        #pragma unroll
        for (int o = 1; o < 32; o <<= 1) {
            int u = __shfl_up_sync(0xffffffffu, incl, o);
            if (lane >= o) incl += u;
        }
        if (lane == 31) wsum[wid] = incl;
        __syncthreads();
        if (wid == 0) {
            int x = wsum[lane];
            #pragma unroll
            for (int o = 1; o < 32; o <<= 1) {
                int u = __shfl_up_sync(0xffffffffu, x, o);
                if (lane >= o) x += u;
            }
            wsum[lane] = x;
        }
        __syncthreads();
        int warp_off = (wid == 0) ? 0 : wsum[wid - 1];
        int excl = s_carry + warp_off + (incl - tot);
        #pragma unroll
        for (int j = 0; j < 8; j++) {
            int idx = idx0 + j;
            if (idx < NN) rowptr[idx + 1] = excl + v[j];
        }
        __syncthreads();
        if (t == 0) s_carry += wsum[31];
        __syncthreads();
    }
}

// scatter edges into CSR slots; accumulate per-node edge-attr sum S
__global__ void scatter_kernel(const int* __restrict__ src, const int* __restrict__ dst,
                               const float* __restrict__ ea, const int* __restrict__ rowptr,
                               int* __restrict__ cursor, int* __restrict__ csr_src,
                               float* __restrict__ S) {
    int e = blockIdx.x * blockDim.x + threadIdx.x;
    if (e >= EE) return;
    int d = dst[e];
    int pos = atomicAdd(&cursor[d], 1);
    csr_src[rowptr[d] + pos] = src[e];
    const float* eap = ea + (size_t)e * 5;
    #pragma unroll
    for (int k = 0; k < 5; k++) atomicAdd(&S[d * 5 + k], eap[k]);
}

// ---------------- dense GEMM: C = (relu?)A @ W ----------------
__global__ void gemm_kernel(const float* __restrict__ A, const float* __restrict__ W,
                            float* __restrict__ C, int n, int relu, int ldw) {
    __shared__ float hsT[64][68];
    __shared__ float Ws[64][64];
    int n0 = blockIdx.x << 6;
    int c0b = blockIdx.y << 6;
    int t = threadIdx.x;

    #pragma unroll
    for (int i = 0; i < 4; i++) {
        int idx = t + i * 256;
        int row = idx >> 4;
        int k4 = (idx & 15) << 2;
        float4 v = make_float4(0.f, 0.f, 0.f, 0.f);
        if (n0 + row < n) v = *(const float4*)(A + (size_t)(n0 + row) * 64 + k4);
        if (relu) {
            v.x = fmaxf(v.x, 0.f); v.y = fmaxf(v.y, 0.f);
            v.z = fmaxf(v.z, 0.f); v.w = fmaxf(v.w, 0.f);
        }
        hsT[k4 + 0][row] = v.x; hsT[k4 + 1][row] = v.y;
        hsT[k4 + 2][row] = v.z; hsT[k4 + 3][row] = v.w;
    }
    #pragma unroll
    for (int i = 0; i < 4; i++) {
        int idx = t + i * 256;
        int k = idx >> 4;
        int c4 = (idx & 15) << 2;
        *(float4*)&Ws[k][c4] = *(const float4*)(W + (size_t)k * ldw + c0b + c4);
    }
    __syncthreads();

    int tx = t & 15, ty = t >> 4;
    int r0 = ty << 2, c0 = tx << 2;
    float acc[4][4];
    #pragma unroll
    for (int i = 0; i < 4; i++)
        #pragma unroll
        for (int j = 0; j < 4; j++) acc[i][j] = 0.f;

    #pragma unroll
    for (int k = 0; k < 64; k++) {
        float4 a = *(float4*)&hsT[k][r0];
        float4 b = *(float4*)&Ws[k][c0];
        acc[0][0] += a.x * b.x; acc[0][1] += a.x * b.y; acc[0][2] += a.x * b.z; acc[0][3] += a.x * b.w;
        acc[1][0] += a.y * b.x; acc[1][1] += a.y * b.y; acc[1][2] += a.y * b.z; acc[1][3] += a.y * b.w;
        acc[2][0] += a.z * b.x; acc[2][1] += a.z * b.y; acc[2][2] += a.z * b.z; acc[2][3] += a.z * b.w;
        acc[3][0] += a.w * b.x; acc[3][1] += a.w * b.y; acc[3][2] += a.w * b.z; acc[3][3] += a.w * b.w;
    }

    #pragma unroll
    for (int i = 0; i < 4; i++) {
        int row = n0 + r0 + i;
        if (row < n) {
            float4 o = make_float4(acc[i][0], acc[i][1], acc[i][2], acc[i][3]);
            *(float4*)(C + (size_t)row * ldw + c0b + c0) = o;
        }
    }
}

// ---------------- edge aggregation (CSR, no atomics) ----------------
// out[n] = sum_{e in-edges} p[src_e] + S[n]@We' + deg(n)*b'
__global__ void agg_kernel(const float* __restrict__ p, const int* __restrict__ csr_src,
                           const int* __restrict__ rowptr, const float* __restrict__ S,
                           const float* __restrict__ We, const float* __restrict__ bp,
                           float* __restrict__ out) {
    __shared__ float sWe[320];
    __shared__ float sbp[64];
    int t = threadIdx.x;
    for (int i = t; i < 384; i += 256) {
        if (i < 320) sWe[i] = We[i];
        else sbp[i - 320] = bp[i - 320];
    }
    __syncthreads();

    int n = blockIdx.x * 8 + (t >> 5);
    int lane = t & 31;
    int start = rowptr[n], end = rowptr[n + 1];
    float s0 = S[n * 5 + 0], s1 = S[n * 5 + 1], s2 = S[n * 5 + 2],
          s3 = S[n * 5 + 3], s4 = S[n * 5 + 4];
    float deg = (float)(end - start);
    int c = lane, c2 = lane + 32;
    float acc0 = deg * sbp[c] + s0 * sWe[c] + s1 * sWe[64 + c] + s2 * sWe[128 + c] +
                 s3 * sWe[192 + c] + s4 * sWe[256 + c];
    float acc1 = deg * sbp[c2] + s0 * sWe[c2] + s1 * sWe[64 + c2] + s2 * sWe[128 + c2] +
                 s3 * sWe[192 + c2] + s4 * sWe[256 + c2];

    int j = start;
    for (; j + 1 < end; j += 2) {
        int sa = csr_src[j], sb = csr_src[j + 1];
        const float* pa = p + (size_t)sa * 64;
        const float* pb = p + (size_t)sb * 64;
        float a0 = pa[c], a1 = pa[c2];
        float b0 = pb[c], b1 = pb[c2];
        acc0 += a0 + b0;
        acc1 += a1 + b1;
    }
    if (j < end) {
        int sa = csr_src[j];
        acc0 += p[(size_t)sa * 64 + c];
        acc1 += p[(size_t)sa * 64 + c2];
    }
    out[(size_t)n * 64 + c] = acc0;
    out[(size_t)n * 64 + c2] = acc1;
}

// ---------------- GAT attention coefficients ----------------
__global__ void attn_kernel(const float* __restrict__ g, const float* __restrict__ att_src,
                            const float* __restrict__ att_dst, float* __restrict__ asrc,
                            float* __restrict__ adst, int n) {
    int w = (blockIdx.x * blockDim.x + threadIdx.x) >> 5;
    int lane = threadIdx.x & 31;
    if (w >= n) return;
    const float* gr = g + (size_t)w * 128;
    float v0 = gr[lane], v1 = gr[lane + 32], v2 = gr[lane + 64], v3 = gr[lane + 96];
    float s0 = v0 * att_src[lane] + v1 * att_src[lane + 32];
    float s1 = v2 * att_src[64 + lane] + v3 * att_src[96 + lane];
    float d0 = v0 * att_dst[lane] + v1 * att_dst[lane + 32];
    float d1 = v2 * att_dst[64 + lane] + v3 * att_dst[96 + lane];
    #pragma unroll
    for (int o = 16; o; o >>= 1) {
        s0 += __shfl_down_sync(0xffffffffu, s0, o);
        s1 += __shfl_down_sync(0xffffffffu, s1, o);
        d0 += __shfl_down_sync(0xffffffffu, d0, o);
        d1 += __shfl_down_sync(0xffffffffu, d1, o);
    }
    if (lane == 0) {
        asrc[w * 2] = s0; asrc[w * 2 + 1] = s1;
        adst[w * 2] = d0; adst[w * 2 + 1] = d1;
    }
}

// ---------------- fused GAT: softmax + aggregate + head-mean + bias ----------------
__global__ void gat_kernel(const int* __restrict__ csr_src, const int* __restrict__ rowptr,
                           const float2* __restrict__ aS, const float2* __restrict__ aD,
                           const float* __restrict__ g, const float* __restrict__ b_gat,
                           float* __restrict__ out) {
    int n = blockIdx.x * 8 + (threadIdx.x >> 5);
    int lane = threadIdx.x & 31;
    int start = rowptr[n], end = rowptr[n + 1];
    float2 ad = aD[n];
    float m0 = -1e30f, m1 = -1e30f;
    for (int j = start; j < end; j++) {
        int s = csr_src[j];
        float2 as = aS[s];
        float a0 = lrelu(as.x + ad.x), a1 = lrelu(as.y + ad.y);
        m0 = fmaxf(m0, a0);
        m1 = fmaxf(m1, a1);
    }
    float acc0 = 0.f, acc1 = 0.f, acc2 = 0.f, acc3 = 0.f, den0 = 0.f, den1 = 0.f;
    for (int j = start; j < end; j++) {
        int s = csr_src[j];
        float2 as = aS[s];
        float a0 = lrelu(as.x + ad.x), a1 = lrelu(as.y + ad.y);
        float w0 = __expf(a0 - m0), w1 = __expf(a1 - m1);
        den0 += w0;
        den1 += w1;
        const float* gs = g + (size_t)s * 128;
        acc0 += w0 * gs[lane];
        acc1 += w0 * gs[lane + 32];
        acc2 += w1 * gs[lane + 64];
        acc3 += w1 * gs[lane + 96];
    }
    float id0 = 1.f / (den0 + 1e-16f);
    float id1 = 1.f / (den1 + 1e-16f);
    out[(size_t)n * 64 + lane]      = 0.5f * (acc0 * id0 + acc2 * id1) + b_gat[lane];
    out[(size_t)n * 64 + lane + 32] = 0.5f * (acc1 * id0 + acc3 * id1) + b_gat[lane + 32];
}

// ---------------- launch ----------------
extern "C" void kernel_launch(void* const* d_in, const int* in_sizes, int n_in,
                              void* d_out, int out_size) {
    const float* x = (const float*)d_in[0];
    const int* ei = (const int*)d_in[1];
    const float* ea = (const float*)d_in[2];
    const int* src = ei;
    const int* dst = ei + EE;
    const float* Wp[18];
    for (int i = 0; i < 18; i++) Wp[i] = (const float*)d_in[3 + i];
    const float* w_gat = (const float*)d_in[21];
    const float* att_src = (const float*)d_in[22];
    const float* att_dst = (const float*)d_in[23];
    const float* b_gat = (const float*)d_in[24];
    float* out = (float*)d_out;

    float *h1, *h2, *p, *gg, *asrc, *adst, *Wn, *We, *bp, *S;
    int *cnt, *cursor, *rowptr, *csr_src;
    cudaGetSymbolAddress((void**)&h1, g_h1);
    cudaGetSymbolAddress((void**)&h2, g_h2);
    cudaGetSymbolAddress((void**)&p, g_p);
    cudaGetSymbolAddress((void**)&gg, g_g);
    cudaGetSymbolAddress((void**)&asrc, g_asrc);
    cudaGetSymbolAddress((void**)&adst, g_adst);
    cudaGetSymbolAddress((void**)&Wn, g_Wn);
    cudaGetSymbolAddress((void**)&We, g_We);
    cudaGetSymbolAddress((void**)&bp, g_bp);
    cudaGetSymbolAddress((void**)&cnt, g_cnt);
    cudaGetSymbolAddress((void**)&cursor, g_cursor);
    cudaGetSymbolAddress((void**)&rowptr, g_rowptr);
    cudaGetSymbolAddress((void**)&csr_src, g_csr_src);
    cudaGetSymbolAddress((void**)&S, g_S);

    // ---- CSR build (independent of weights) ----
    zero4_kernel<<<98, 256>>>((float4*)cnt, NN / 4);
    zero4_kernel<<<98, 256>>>((float4*)cursor, NN / 4);
    zero4_kernel<<<489, 256>>>((float4*)S, NN * 5 / 4);
    count_kernel<<<EE / 256, 256>>>(dst, cnt);
    scan_kernel<<<1, 1024>>>(cnt, rowptr);
    scatter_kernel<<<EE / 256, 256>>>(src, dst, ea, rowptr, cursor, csr_src, S);

    // ---- fold weights ----
    for (int i = 0; i < 3; i++) {
        fold_kernel<<<18, 256>>>(Wp[6 * i + 0], Wp[6 * i + 1], Wp[6 * i + 2], Wp[6 * i + 3],
                                 Wp[6 * i + 4], Wp[6 * i + 5],
                                 Wn + i * 4096, We + i * 320, bp + i * 64);
    }

    const int gb = (NN + 63) / 64;   // 1563
    const int NB = NN / 8;           // 12500 (warp-per-node blocks)

    // layer 1
    gemm_kernel<<<dim3(gb, 1), 256>>>(x, Wn + 0 * 4096, p, NN, 0, 64);
    agg_kernel<<<NB, 256>>>(p, csr_src, rowptr, S, We + 0 * 320, bp + 0 * 64, h1);
    // layer 2
    gemm_kernel<<<dim3(gb, 1), 256>>>(h1, Wn + 1 * 4096, p, NN, 1, 64);
    agg_kernel<<<NB, 256>>>(p, csr_src, rowptr, S, We + 1 * 320, bp + 1 * 64, h2);
    // layer 3
    gemm_kernel<<<dim3(gb, 1), 256>>>(h2, Wn + 2 * 4096, p, NN, 1, 64);
    agg_kernel<<<NB, 256>>>(p, csr_src, rowptr, S, We + 2 * 320, bp + 2 * 64, h1);

    // GAT projection g = relu(h) @ w_gat (64 -> 128)
    gemm_kernel<<<dim3(gb, 2), 256>>>(h1, w_gat, gg, NN, 1, 128);
    attn_kernel<<<(NN + 7) / 8, 256>>>(gg, att_src, att_dst, asrc, adst, NN);
    gat_kernel<<<NB, 256>>>(csr_src, rowptr, (const float2*)asrc, (const float2*)adst,
                            gg, b_gat, out);
}